// round 14
// baseline (speedup 1.0000x reference)
#include <cuda_runtime.h>

#define NPTS     200000
#define NREL     128
#define SCT_PTS  1024
#define NBLK     ((NPTS + SCT_PTS - 1) / SCT_PTS)   // 196
#define CELLCAP  32          // per-(relation, window) capacity; mean 8, sd 2.8
#define CTAS_PER_REL 6
#define GRID_MAIN (NREL * CTAS_PER_REL)   // 768, uniform 6 CTAs/relation
#define THREADS  256
#define WSTRIDE  36          // words per lane in smem weight tile (bank swizzle)

// ---- device scratch (no allocations). Everything below is rewritten by
//      k_scatter each launch (or never consumed past the written count). ----
__device__ int g_cellcnt[NREL * NBLK];
__device__ int g_cursor[NREL];
__device__ int g_pids[NREL * NBLK * CELLCAP];

// Scatter (single pass, R13 winner): window blk bins its 1024 points into
// its OWN fixed cell per relation; counts published after the pass from the
// smem cursors. Block 0 rezeroes the work-stealing cursors. Overflow beyond
// CELLCAP (>8 sigma) computed inline.
__global__ void __launch_bounds__(256)
k_scatter(const int* __restrict__ rel, int n,
          const float* __restrict__ x,
          const float* __restrict__ w,
          float* __restrict__ out) {
    __shared__ int s_cur[NREL];

    int blk = blockIdx.x;
    if (blk == 0) {
        for (int i = threadIdx.x; i < NREL; i += blockDim.x) g_cursor[i] = 0;
    }

    int start = blk * SCT_PTS;
    int cnt = n - start;
    if (cnt > SCT_PTS) cnt = SCT_PTS;

    for (int i = threadIdx.x; i < NREL; i += blockDim.x) s_cur[i] = 0;
    __syncthreads();

    for (int i = threadIdx.x; i < cnt; i += blockDim.x) {
        int r = __ldg(rel + start + i);
        int pos = atomicAdd(&s_cur[r], 1);
        int p = start + i;
        if (pos < CELLCAP) {
            g_pids[(r * NBLK + blk) * CELLCAP + pos] = p;
        } else {
            // Dead-in-practice overflow: compute this point directly.
            const float* xr = x + (size_t)p * 128;
            float* orow = out + (size_t)p * 128;
            for (int bb = 0; bb < 16; bb++) {
                const float* wb = w + (size_t)((r * 16 + bb) * 8) * 8;
                for (int o = 0; o < 8; o++) {
                    float acc = 0.f;
                    for (int ii = 0; ii < 8; ii++)
                        acc = fmaf(xr[bb * 8 + ii], wb[ii * 8 + o], acc);
                    orow[bb * 8 + o] = acc;
                }
            }
        }
    }
    __syncthreads();

    for (int i = threadIdx.x; i < NREL; i += blockDim.x) {
        int c = s_cur[i];
        g_cellcnt[i * NBLK + blk] = (c > CELLCAP) ? CELLCAP : c;
    }

    __syncthreads();
#if __CUDA_ARCH__ >= 900
    cudaTriggerProgrammaticLaunchCompletion();
#endif
}

// Per-relation steal/compute loop (R10 winner, verbatim): single-cell
// steals, depth-1 prefetch, batch-2 fused inner loop (one weight LDS per
// two points).
__device__ __forceinline__ void run_rel(
    int r, const float4* __restrict__ wl,
    const float4* __restrict__ x4, float4* __restrict__ out4,
    int ncell, int b, int lane) {
#define STEAL(C)                                                     \
    {                                                                \
        int t = 0;                                                   \
        if (lane == 0) t = atomicAdd(&g_cursor[r], 1);               \
        (C) = __shfl_sync(0xffffffffu, t, 0);                        \
    }

    int cA;
    STEAL(cA)
    int cntA = 0, pidA = 0;
    if (cA < ncell) {
        int ci = r * NBLK + cA;
        cntA = __ldg(&g_cellcnt[ci]);
        pidA = __ldg(g_pids + (size_t)ci * CELLCAP + lane);
    }

    while (cA < ncell) {
        int cB;
        STEAL(cB)
        int cntB = 0, pidB = 0;
        if (cB < ncell) {
            int ci = r * NBLK + cB;
            cntB = __ldg(&g_cellcnt[ci]);
            pidB = __ldg(g_pids + (size_t)ci * CELLCAP + lane);
        }

        int k = 0;
        for (; k + 2 <= cntA; k += 2) {
            int p0 = __shfl_sync(0xffffffffu, pidA, k);
            int p1 = __shfl_sync(0xffffffffu, pidA, k + 1);
            float4 xa0 = __ldg(x4 + (size_t)p0 * 32 + 2 * b);
            float4 xb0 = __ldg(x4 + (size_t)p0 * 32 + 2 * b + 1);
            float4 xa1 = __ldg(x4 + (size_t)p1 * 32 + 2 * b);
            float4 xb1 = __ldg(x4 + (size_t)p1 * 32 + 2 * b + 1);

            float xs0[8] = {xa0.x, xa0.y, xa0.z, xa0.w,
                            xb0.x, xb0.y, xb0.z, xb0.w};
            float xs1[8] = {xa1.x, xa1.y, xa1.z, xa1.w,
                            xb1.x, xb1.y, xb1.z, xb1.w};
            float u0 = 0.f, u1 = 0.f, u2 = 0.f, u3 = 0.f;
            float v0 = 0.f, v1 = 0.f, v2 = 0.f, v3 = 0.f;
#pragma unroll
            for (int i = 0; i < 8; i++) {
                float4 w = wl[i];             // ONE LDS, used by BOTH points
                u0 = fmaf(xs0[i], w.x, u0);
                u1 = fmaf(xs0[i], w.y, u1);
                u2 = fmaf(xs0[i], w.z, u2);
                u3 = fmaf(xs0[i], w.w, u3);
                v0 = fmaf(xs1[i], w.x, v0);
                v1 = fmaf(xs1[i], w.y, v1);
                v2 = fmaf(xs1[i], w.z, v2);
                v3 = fmaf(xs1[i], w.w, v3);
            }
            out4[(size_t)p0 * 32 + lane] = make_float4(u0, u1, u2, u3);
            out4[(size_t)p1 * 32 + lane] = make_float4(v0, v1, v2, v3);
        }
        if (k < cntA) {
            int p = __shfl_sync(0xffffffffu, pidA, k);
            float4 xa = __ldg(x4 + (size_t)p * 32 + 2 * b);
            float4 xb = __ldg(x4 + (size_t)p * 32 + 2 * b + 1);
            float xs[8] = {xa.x, xa.y, xa.z, xa.w, xb.x, xb.y, xb.z, xb.w};
            float u0 = 0.f, u1 = 0.f, u2 = 0.f, u3 = 0.f;
#pragma unroll
            for (int i = 0; i < 8; i++) {
                float4 w = wl[i];
                u0 = fmaf(xs[i], w.x, u0);
                u1 = fmaf(xs[i], w.y, u1);
                u2 = fmaf(xs[i], w.z, u2);
                u3 = fmaf(xs[i], w.w, u3);
            }
            out4[(size_t)p * 32 + lane] = make_float4(u0, u1, u2, u3);
        }

        cA = cB; cntA = cntB; pidA = pidB;
    }
#undef STEAL
}

// Main — DUAL-RELATION tail filling. Each CTA stages TWO relations'
// weight tiles (primary r0 = blockIdx%128, secondary r1 = (r0+64)%128;
// 9.2KB smem, still 6 CTAs/SM). A warp drains r0 exactly as the R10
// winner (identical quantum/granularity), and only when r0's cursor is
// exhausted does it steal from r1 — so each relation is served by 6
// primary + up to 6 tail-filling secondary CTAs. Worst case neutral
// (phase 2 exits on first steal); best case fills the ~20% occupancy
// hole left by per-relation finish-time skew.
__global__ void __launch_bounds__(THREADS, 6)
k_main(const float4* __restrict__ x4,
       const float4* __restrict__ w4,
       float4* __restrict__ out4,
       int ncell) {
    __shared__ float s_w[2 * 32 * WSTRIDE];   // 9216 B: two weight tiles

    int r0   = blockIdx.x % NREL;
    int r1   = (r0 + 64) % NREL;
    int tid  = threadIdx.x;
    int lane = tid & 31;
    int b    = lane >> 1;

    // ---- independent preamble (PDL): stage BOTH weight tiles ----
    // thread t -> (l = t>>3, i = t&7):
    //   s_w[l*36 + i*4 ..]           = W[r0][l>>1][i][4*(l&1) ..]
    //   s_w[32*36 + l*36 + i*4 ..]   = W[r1][l>>1][i][4*(l&1) ..]
    {
        int l  = tid >> 3;
        int i  = tid & 7;
        int bb = l >> 1;
        int hh = l & 1;
        float4 w0 = __ldg(w4 + (size_t)((r0 * 16 + bb) * 8 + i) * 2 + hh);
        float4 w1 = __ldg(w4 + (size_t)((r1 * 16 + bb) * 8 + i) * 2 + hh);
        *(float4*)(s_w + l * WSTRIDE + i * 4) = w0;
        *(float4*)(s_w + 32 * WSTRIDE + l * WSTRIDE + i * 4) = w1;
    }

#if __CUDA_ARCH__ >= 900
    cudaGridDependencySynchronize();
#endif
    __syncthreads();

    const float4* wl0 = (const float4*)(s_w + lane * WSTRIDE);
    const float4* wl1 = (const float4*)(s_w + 32 * WSTRIDE + lane * WSTRIDE);

    run_rel(r0, wl0, x4, out4, ncell, b, lane);   // phase 1: primary
    run_rel(r1, wl1, x4, out4, ncell, b, lane);   // phase 2: tail fill
}

extern "C" void kernel_launch(void* const* d_in, const int* in_sizes, int n_in,
                              void* d_out, int out_size) {
    const float* x      = (const float*)d_in[0];   // [NPTS, 128] f32
    const float* blocks = (const float*)d_in[1];   // [128,16,8,8] f32
    const int*   rel    = (const int*)d_in[2];     // [NPTS] i32
    int n = in_sizes[2];
    if (n > NPTS) n = NPTS;  // scratch bound

    int nblk = (n + SCT_PTS - 1) / SCT_PTS;        // 196

    k_scatter<<<nblk, 256>>>(rel, n, x, blocks, (float*)d_out);

    // k_main with PDL: launches early, stages weights, grid-dependency-
    // syncs before reading scatter outputs.
    cudaLaunchConfig_t cfg = {};
    cfg.gridDim  = dim3(GRID_MAIN);
    cfg.blockDim = dim3(THREADS);
    cfg.dynamicSmemBytes = 0;
    cfg.stream   = 0;
    cudaLaunchAttribute attr[1];
    attr[0].id = cudaLaunchAttributeProgrammaticStreamSerialization;
    attr[0].val.programmaticStreamSerializationAllowed = 1;
    cfg.attrs    = attr;
    cfg.numAttrs = 1;
    cudaLaunchKernelEx(&cfg, k_main,
                       (const float4*)x, (const float4*)blocks,
                       (float4*)d_out, nblk);
}

// round 15
// speedup vs baseline: 1.0451x; 1.0451x over previous
#include <cuda_runtime.h>

#define NPTS     200000
#define NREL     128
#define SCT_PTS  1024
#define NBLK     ((NPTS + SCT_PTS - 1) / SCT_PTS)   // 196
#define CELLCAP  32          // per-(relation, window) capacity; mean 8, sd 2.8
#define CTAS_PER_REL 6
#define GRID_MAIN (NREL * CTAS_PER_REL)   // 768, uniform 6 CTAs/relation
#define THREADS  256
#define WSTRIDE  36          // words per lane in smem weight tile (bank swizzle)

// ---- device scratch (no allocations). Everything below is rewritten by
//      k_scatter each launch (or never consumed past the written count). ----
__device__ int g_cellcnt[NREL * NBLK];
__device__ int g_cursor[NREL];
__device__ int g_pids[NREL * NBLK * CELLCAP];

// Scatter (SORTED): window blk counting-sorts its 1024 points by relation
// in smem, then writes g_pids in bin-sorted order so consecutive threads
// hit consecutive addresses (~8-int runs) — ~8x fewer store sectors than
// the old per-point scattered 4B stores. rel reads are int4-vectorized.
// Block 0 rezeroes the work-stealing cursors. Overflow beyond CELLCAP
// (>8 sigma) computed inline; its sorted slots are skipped at write time.
__global__ void __launch_bounds__(256)
k_scatter(const int* __restrict__ rel, int n,
          const float* __restrict__ x,
          const float* __restrict__ w,
          float* __restrict__ out) {
    __shared__ int  s_rel[SCT_PTS];
    __shared__ int  s_out[SCT_PTS];           // sorted global pids
    __shared__ unsigned char s_bin[SCT_PTS];  // bin of each sorted slot
    __shared__ int  s_hist[NREL];
    __shared__ int  s_base[NREL];
    __shared__ int  s_cur[NREL];
    __shared__ int  s_scan[NREL];

    int blk = blockIdx.x;
    int tid = threadIdx.x;
    if (blk == 0) {
        for (int i = tid; i < NREL; i += blockDim.x) g_cursor[i] = 0;
    }

    int start = blk * SCT_PTS;
    int cnt = n - start;
    if (cnt > SCT_PTS) cnt = SCT_PTS;

    for (int i = tid; i < NREL; i += blockDim.x) {
        s_hist[i] = 0;
        s_cur[i]  = 0;
    }
    __syncthreads();

    // ---- pass 1: vectorized read + histogram ----
    // 256 threads x 4 ints = 1024 (full windows use the int4 fast path)
    if (cnt == SCT_PTS) {
        int4 v = __ldg((const int4*)(rel + start) + tid);
        s_rel[4 * tid + 0] = v.x;
        s_rel[4 * tid + 1] = v.y;
        s_rel[4 * tid + 2] = v.z;
        s_rel[4 * tid + 3] = v.w;
        atomicAdd(&s_hist[v.x], 1);
        atomicAdd(&s_hist[v.y], 1);
        atomicAdd(&s_hist[v.z], 1);
        atomicAdd(&s_hist[v.w], 1);
    } else {
        for (int i = tid; i < cnt; i += blockDim.x) {
            int r = __ldg(rel + start + i);
            s_rel[i] = r;
            atomicAdd(&s_hist[r], 1);
        }
    }
    __syncthreads();

    // ---- exclusive scan over 128 bins (threads 0..127) + publish counts ----
    if (tid < NREL) {
        int c = s_hist[tid];
        s_scan[tid] = c;
        g_cellcnt[tid * NBLK + blk] = (c > CELLCAP) ? CELLCAP : c;
    }
    __syncthreads();
#pragma unroll
    for (int d = 1; d < NREL; d <<= 1) {
        int v = 0;
        if (tid < NREL && tid >= d) v = s_scan[tid - d];
        __syncthreads();
        if (tid < NREL) s_scan[tid] += v;
        __syncthreads();
    }
    if (tid < NREL) s_base[tid] = s_scan[tid] - s_hist[tid];
    __syncthreads();

    // ---- pass 2: place into bin-sorted smem slots ----
    for (int i = tid; i < cnt; i += blockDim.x) {
        int r   = s_rel[i];
        int loc = atomicAdd(&s_cur[r], 1);
        int p   = start + i;
        int pos = s_base[r] + loc;
        s_out[pos] = p;
        s_bin[pos] = (unsigned char)r;
        if (loc >= CELLCAP) {
            // Dead-in-practice overflow: compute this point directly.
            const float* xr = x + (size_t)p * 128;
            float* orow = out + (size_t)p * 128;
            for (int bb = 0; bb < 16; bb++) {
                const float* wb = w + (size_t)((r * 16 + bb) * 8) * 8;
                for (int o = 0; o < 8; o++) {
                    float acc = 0.f;
                    for (int ii = 0; ii < 8; ii++)
                        acc = fmaf(xr[bb * 8 + ii], wb[ii * 8 + o], acc);
                    orow[bb * 8 + o] = acc;
                }
            }
        }
    }
    __syncthreads();

    // ---- pass 3: coalesced writes (consecutive i -> consecutive addrs) ----
    for (int i = tid; i < cnt; i += blockDim.x) {
        int r      = s_bin[i];
        int within = i - s_base[r];
        if (within < CELLCAP)
            g_pids[(r * NBLK + blk) * CELLCAP + within] = s_out[i];
    }

    __syncthreads();
#if __CUDA_ARCH__ >= 900
    cudaTriggerProgrammaticLaunchCompletion();
#endif
}

// Main — EXACT R13/R10 winner, FROZEN (40.2us confirmed twice; R11/R12/R14
// scheduling perturbations all regressed): CTA = one relation, 8 warps/CTA,
// 6 CTAs/relation = 48 warps/relation, single wave, regs<=42. Relation's
// 4KB weight tile in bank-swizzled SHARED MEMORY (lane stride 36 words,
// conflict-free LDS.128). lane = 2b+h owns block b, out-half h. Batch-2
// fused inner loop: each weight float4 LDS'd once, applied to both points.
// Single-cell work stealing with depth-1 prefetch.
__global__ void __launch_bounds__(THREADS, 6)
k_main(const float4* __restrict__ x4,
       const float4* __restrict__ w4,
       float4* __restrict__ out4,
       int ncell) {
    __shared__ float s_w[32 * WSTRIDE];   // 4608 B

    int r    = blockIdx.x % NREL;
    int tid  = threadIdx.x;
    int lane = tid & 31;
    int b    = lane >> 1;

    // ---- independent preamble (PDL): stage weights ----
    {
        int l  = tid >> 3;
        int i  = tid & 7;
        int bb = l >> 1;
        int hh = l & 1;
        float4 w = __ldg(w4 + (size_t)((r * 16 + bb) * 8 + i) * 2 + hh);
        *(float4*)(s_w + l * WSTRIDE + i * 4) = w;
    }

#if __CUDA_ARCH__ >= 900
    cudaGridDependencySynchronize();
#endif
    __syncthreads();

    const float4* wl = (const float4*)(s_w + lane * WSTRIDE);  // wl[i], i<8

#define STEAL(C)                                                     \
    {                                                                \
        int t = 0;                                                   \
        if (lane == 0) t = atomicAdd(&g_cursor[r], 1);               \
        (C) = __shfl_sync(0xffffffffu, t, 0);                        \
    }

    int cA;
    STEAL(cA)
    int cntA = 0, pidA = 0;
    if (cA < ncell) {
        int ci = r * NBLK + cA;
        cntA = __ldg(&g_cellcnt[ci]);
        pidA = __ldg(g_pids + (size_t)ci * CELLCAP + lane);
    }

    while (cA < ncell) {
        // prefetch next cell while processing this one
        int cB;
        STEAL(cB)
        int cntB = 0, pidB = 0;
        if (cB < ncell) {
            int ci = r * NBLK + cB;
            cntB = __ldg(&g_cellcnt[ci]);
            pidB = __ldg(g_pids + (size_t)ci * CELLCAP + lane);
        }

        int k = 0;
        for (; k + 2 <= cntA; k += 2) {
            int p0 = __shfl_sync(0xffffffffu, pidA, k);
            int p1 = __shfl_sync(0xffffffffu, pidA, k + 1);
            float4 xa0 = __ldg(x4 + (size_t)p0 * 32 + 2 * b);
            float4 xb0 = __ldg(x4 + (size_t)p0 * 32 + 2 * b + 1);
            float4 xa1 = __ldg(x4 + (size_t)p1 * 32 + 2 * b);
            float4 xb1 = __ldg(x4 + (size_t)p1 * 32 + 2 * b + 1);

            float xs0[8] = {xa0.x, xa0.y, xa0.z, xa0.w,
                            xb0.x, xb0.y, xb0.z, xb0.w};
            float xs1[8] = {xa1.x, xa1.y, xa1.z, xa1.w,
                            xb1.x, xb1.y, xb1.z, xb1.w};
            float u0 = 0.f, u1 = 0.f, u2 = 0.f, u3 = 0.f;
            float v0 = 0.f, v1 = 0.f, v2 = 0.f, v3 = 0.f;
#pragma unroll
            for (int i = 0; i < 8; i++) {
                float4 w = wl[i];             // ONE LDS, used by BOTH points
                u0 = fmaf(xs0[i], w.x, u0);
                u1 = fmaf(xs0[i], w.y, u1);
                u2 = fmaf(xs0[i], w.z, u2);
                u3 = fmaf(xs0[i], w.w, u3);
                v0 = fmaf(xs1[i], w.x, v0);
                v1 = fmaf(xs1[i], w.y, v1);
                v2 = fmaf(xs1[i], w.z, v2);
                v3 = fmaf(xs1[i], w.w, v3);
            }
            out4[(size_t)p0 * 32 + lane] = make_float4(u0, u1, u2, u3);
            out4[(size_t)p1 * 32 + lane] = make_float4(v0, v1, v2, v3);
        }
        if (k < cntA) {
            int p = __shfl_sync(0xffffffffu, pidA, k);
            float4 xa = __ldg(x4 + (size_t)p * 32 + 2 * b);
            float4 xb = __ldg(x4 + (size_t)p * 32 + 2 * b + 1);
            float xs[8] = {xa.x, xa.y, xa.z, xa.w, xb.x, xb.y, xb.z, xb.w};
            float u0 = 0.f, u1 = 0.f, u2 = 0.f, u3 = 0.f;
#pragma unroll
            for (int i = 0; i < 8; i++) {
                float4 w = wl[i];
                u0 = fmaf(xs[i], w.x, u0);
                u1 = fmaf(xs[i], w.y, u1);
                u2 = fmaf(xs[i], w.z, u2);
                u3 = fmaf(xs[i], w.w, u3);
            }
            out4[(size_t)p * 32 + lane] = make_float4(u0, u1, u2, u3);
        }

        cA = cB; cntA = cntB; pidA = pidB;
    }
#undef STEAL
}

extern "C" void kernel_launch(void* const* d_in, const int* in_sizes, int n_in,
                              void* d_out, int out_size) {
    const float* x      = (const float*)d_in[0];   // [NPTS, 128] f32
    const float* blocks = (const float*)d_in[1];   // [128,16,8,8] f32
    const int*   rel    = (const int*)d_in[2];     // [NPTS] i32
    int n = in_sizes[2];
    if (n > NPTS) n = NPTS;  // scratch bound

    int nblk = (n + SCT_PTS - 1) / SCT_PTS;        // 196

    k_scatter<<<nblk, 256>>>(rel, n, x, blocks, (float*)d_out);

    // k_main with PDL: launches early, stages weights, grid-dependency-
    // syncs before reading scatter outputs.
    cudaLaunchConfig_t cfg = {};
    cfg.gridDim  = dim3(GRID_MAIN);
    cfg.blockDim = dim3(THREADS);
    cfg.dynamicSmemBytes = 0;
    cfg.stream   = 0;
    cudaLaunchAttribute attr[1];
    attr[0].id = cudaLaunchAttributeProgrammaticStreamSerialization;
    attr[0].val.programmaticStreamSerializationAllowed = 1;
    cfg.attrs    = attr;
    cfg.numAttrs = 1;
    cudaLaunchKernelEx(&cfg, k_main,
                       (const float4*)x, (const float4*)blocks,
                       (float4*)d_out, nblk);
}

// round 16
// speedup vs baseline: 1.0905x; 1.0435x over previous
#include <cuda_runtime.h>

#define NPTS     200000
#define NREL     128
#define SCT_PTS  1024
#define NBLK     ((NPTS + SCT_PTS - 1) / SCT_PTS)   // 196
#define CELLCAP  32          // per-(relation, window) capacity; mean 8, sd 2.8
#define CTAS_PER_REL 6
#define GRID_MAIN (NREL * CTAS_PER_REL)   // 768, uniform 6 CTAs/relation
#define THREADS  256
#define WSTRIDE  36          // words per lane in smem weight tile (bank swizzle)

// ---- device scratch (no allocations). Everything below is rewritten by
//      k_scatter each launch (or never consumed past the written count). ----
__device__ int g_cellcnt[NREL * NBLK];
__device__ int g_cursor[NREL];
__device__ int g_pids[NREL * NBLK * CELLCAP];

// Scatter (SORTED, fast scan): window blk counting-sorts its 1024 points by
// relation in smem, then writes g_pids in bin-sorted ascending-pid order
// (coalesced stores; also gives k_main better x locality — R15 measured
// k_main 40.2 -> 38.7 from this). The 128-bin exclusive scan is now a
// warp-shuffle scan (2 block barriers instead of 14). Block 0 rezeroes the
// work-stealing cursors. Overflow beyond CELLCAP computed inline.
__global__ void __launch_bounds__(256)
k_scatter(const int* __restrict__ rel, int n,
          const float* __restrict__ x,
          const float* __restrict__ w,
          float* __restrict__ out) {
    __shared__ int  s_rel[SCT_PTS];
    __shared__ int  s_out[SCT_PTS];           // sorted global pids
    __shared__ unsigned char s_bin[SCT_PTS];  // bin of each sorted slot
    __shared__ int  s_hist[NREL];
    __shared__ int  s_base[NREL];
    __shared__ int  s_cur[NREL];
    __shared__ int  s_wsum[4];

    int blk = blockIdx.x;
    int tid = threadIdx.x;
    if (blk == 0) {
        for (int i = tid; i < NREL; i += blockDim.x) g_cursor[i] = 0;
    }

    int start = blk * SCT_PTS;
    int cnt = n - start;
    if (cnt > SCT_PTS) cnt = SCT_PTS;

    for (int i = tid; i < NREL; i += blockDim.x) {
        s_hist[i] = 0;
        s_cur[i]  = 0;
    }
    __syncthreads();

    // ---- pass 1: vectorized read + histogram ----
    if (cnt == SCT_PTS) {
        int4 v = __ldg((const int4*)(rel + start) + tid);
        s_rel[4 * tid + 0] = v.x;
        s_rel[4 * tid + 1] = v.y;
        s_rel[4 * tid + 2] = v.z;
        s_rel[4 * tid + 3] = v.w;
        atomicAdd(&s_hist[v.x], 1);
        atomicAdd(&s_hist[v.y], 1);
        atomicAdd(&s_hist[v.z], 1);
        atomicAdd(&s_hist[v.w], 1);
    } else {
        for (int i = tid; i < cnt; i += blockDim.x) {
            int r = __ldg(rel + start + i);
            s_rel[i] = r;
            atomicAdd(&s_hist[r], 1);
        }
    }
    __syncthreads();

    // ---- exclusive scan over 128 bins: warp-shuffle scan, 2 barriers ----
    int myc = 0, incl = 0;
    if (tid < NREL) {
        int lane = tid & 31;
        int wid  = tid >> 5;           // 0..3
        myc  = s_hist[tid];
        incl = myc;
#pragma unroll
        for (int d = 1; d < 32; d <<= 1) {
            int t = __shfl_up_sync(0xffffffffu, incl, d);
            if (lane >= d) incl += t;
        }
        if (lane == 31) s_wsum[wid] = incl;
        g_cellcnt[tid * NBLK + blk] = (myc > CELLCAP) ? CELLCAP : myc;
    }
    __syncthreads();
    if (tid < NREL) {
        int wid = tid >> 5;
        int off = 0;
#pragma unroll
        for (int j = 0; j < 3; j++)
            if (wid > j) off += s_wsum[j];
        s_base[tid] = off + incl - myc;   // exclusive prefix
    }
    __syncthreads();

    // ---- pass 2: place into bin-sorted smem slots ----
    for (int i = tid; i < cnt; i += blockDim.x) {
        int r   = s_rel[i];
        int loc = atomicAdd(&s_cur[r], 1);
        int p   = start + i;
        int pos = s_base[r] + loc;
        s_out[pos] = p;
        s_bin[pos] = (unsigned char)r;
        if (loc >= CELLCAP) {
            // Dead-in-practice overflow: compute this point directly.
            const float* xr = x + (size_t)p * 128;
            float* orow = out + (size_t)p * 128;
            for (int bb = 0; bb < 16; bb++) {
                const float* wb = w + (size_t)((r * 16 + bb) * 8) * 8;
                for (int o = 0; o < 8; o++) {
                    float acc = 0.f;
                    for (int ii = 0; ii < 8; ii++)
                        acc = fmaf(xr[bb * 8 + ii], wb[ii * 8 + o], acc);
                    orow[bb * 8 + o] = acc;
                }
            }
        }
    }
    __syncthreads();

    // ---- pass 3: coalesced writes (consecutive i -> consecutive addrs) ----
    for (int i = tid; i < cnt; i += blockDim.x) {
        int r      = s_bin[i];
        int within = i - s_base[r];
        if (within < CELLCAP)
            g_pids[(r * NBLK + blk) * CELLCAP + within] = s_out[i];
    }

    __syncthreads();
#if __CUDA_ARCH__ >= 900
    cudaTriggerProgrammaticLaunchCompletion();
#endif
}

// Main — R13/R10 loop structure FROZEN (every scheduling perturbation in
// R11/R12/R14 regressed). Single change vs R15: STREAMING cache hints —
// x rows are read exactly once (__ldcs) and out rows written exactly once
// (__stcs), keeping L2 free for pids/cellcnt. CTA = one relation, 8
// warps/CTA, 6 CTAs/relation, regs<=42; relation's 4KB weight tile in
// bank-swizzled SHARED MEMORY (lane stride 36 words, conflict-free
// LDS.128). lane = 2b+h owns block b, out-half h. Batch-2 fused inner
// loop; single-cell work stealing with depth-1 prefetch.
__global__ void __launch_bounds__(THREADS, 6)
k_main(const float4* __restrict__ x4,
       const float4* __restrict__ w4,
       float4* __restrict__ out4,
       int ncell) {
    __shared__ float s_w[32 * WSTRIDE];   // 4608 B

    int r    = blockIdx.x % NREL;
    int tid  = threadIdx.x;
    int lane = tid & 31;
    int b    = lane >> 1;

    // ---- independent preamble (PDL): stage weights ----
    {
        int l  = tid >> 3;
        int i  = tid & 7;
        int bb = l >> 1;
        int hh = l & 1;
        float4 w = __ldg(w4 + (size_t)((r * 16 + bb) * 8 + i) * 2 + hh);
        *(float4*)(s_w + l * WSTRIDE + i * 4) = w;
    }

#if __CUDA_ARCH__ >= 900
    cudaGridDependencySynchronize();
#endif
    __syncthreads();

    const float4* wl = (const float4*)(s_w + lane * WSTRIDE);  // wl[i], i<8

#define STEAL(C)                                                     \
    {                                                                \
        int t = 0;                                                   \
        if (lane == 0) t = atomicAdd(&g_cursor[r], 1);               \
        (C) = __shfl_sync(0xffffffffu, t, 0);                        \
    }

    int cA;
    STEAL(cA)
    int cntA = 0, pidA = 0;
    if (cA < ncell) {
        int ci = r * NBLK + cA;
        cntA = __ldg(&g_cellcnt[ci]);
        pidA = __ldg(g_pids + (size_t)ci * CELLCAP + lane);
    }

    while (cA < ncell) {
        // prefetch next cell while processing this one
        int cB;
        STEAL(cB)
        int cntB = 0, pidB = 0;
        if (cB < ncell) {
            int ci = r * NBLK + cB;
            cntB = __ldg(&g_cellcnt[ci]);
            pidB = __ldg(g_pids + (size_t)ci * CELLCAP + lane);
        }

        int k = 0;
        for (; k + 2 <= cntA; k += 2) {
            int p0 = __shfl_sync(0xffffffffu, pidA, k);
            int p1 = __shfl_sync(0xffffffffu, pidA, k + 1);
            float4 xa0 = __ldcs(x4 + (size_t)p0 * 32 + 2 * b);
            float4 xb0 = __ldcs(x4 + (size_t)p0 * 32 + 2 * b + 1);
            float4 xa1 = __ldcs(x4 + (size_t)p1 * 32 + 2 * b);
            float4 xb1 = __ldcs(x4 + (size_t)p1 * 32 + 2 * b + 1);

            float xs0[8] = {xa0.x, xa0.y, xa0.z, xa0.w,
                            xb0.x, xb0.y, xb0.z, xb0.w};
            float xs1[8] = {xa1.x, xa1.y, xa1.z, xa1.w,
                            xb1.x, xb1.y, xb1.z, xb1.w};
            float u0 = 0.f, u1 = 0.f, u2 = 0.f, u3 = 0.f;
            float v0 = 0.f, v1 = 0.f, v2 = 0.f, v3 = 0.f;
#pragma unroll
            for (int i = 0; i < 8; i++) {
                float4 w = wl[i];             // ONE LDS, used by BOTH points
                u0 = fmaf(xs0[i], w.x, u0);
                u1 = fmaf(xs0[i], w.y, u1);
                u2 = fmaf(xs0[i], w.z, u2);
                u3 = fmaf(xs0[i], w.w, u3);
                v0 = fmaf(xs1[i], w.x, v0);
                v1 = fmaf(xs1[i], w.y, v1);
                v2 = fmaf(xs1[i], w.z, v2);
                v3 = fmaf(xs1[i], w.w, v3);
            }
            __stcs(out4 + (size_t)p0 * 32 + lane, make_float4(u0, u1, u2, u3));
            __stcs(out4 + (size_t)p1 * 32 + lane, make_float4(v0, v1, v2, v3));
        }
        if (k < cntA) {
            int p = __shfl_sync(0xffffffffu, pidA, k);
            float4 xa = __ldcs(x4 + (size_t)p * 32 + 2 * b);
            float4 xb = __ldcs(x4 + (size_t)p * 32 + 2 * b + 1);
            float xs[8] = {xa.x, xa.y, xa.z, xa.w, xb.x, xb.y, xb.z, xb.w};
            float u0 = 0.f, u1 = 0.f, u2 = 0.f, u3 = 0.f;
#pragma unroll
            for (int i = 0; i < 8; i++) {
                float4 w = wl[i];
                u0 = fmaf(xs[i], w.x, u0);
                u1 = fmaf(xs[i], w.y, u1);
                u2 = fmaf(xs[i], w.z, u2);
                u3 = fmaf(xs[i], w.w, u3);
            }
            __stcs(out4 + (size_t)p * 32 + lane, make_float4(u0, u1, u2, u3));
        }

        cA = cB; cntA = cntB; pidA = pidB;
    }
#undef STEAL
}

extern "C" void kernel_launch(void* const* d_in, const int* in_sizes, int n_in,
                              void* d_out, int out_size) {
    const float* x      = (const float*)d_in[0];   // [NPTS, 128] f32
    const float* blocks = (const float*)d_in[1];   // [128,16,8,8] f32
    const int*   rel    = (const int*)d_in[2];     // [NPTS] i32
    int n = in_sizes[2];
    if (n > NPTS) n = NPTS;  // scratch bound

    int nblk = (n + SCT_PTS - 1) / SCT_PTS;        // 196

    k_scatter<<<nblk, 256>>>(rel, n, x, blocks, (float*)d_out);

    // k_main with PDL: launches early, stages weights, grid-dependency-
    // syncs before reading scatter outputs.
    cudaLaunchConfig_t cfg = {};
    cfg.gridDim  = dim3(GRID_MAIN);
    cfg.blockDim = dim3(THREADS);
    cfg.dynamicSmemBytes = 0;
    cfg.stream   = 0;
    cudaLaunchAttribute attr[1];
    attr[0].id = cudaLaunchAttributeProgrammaticStreamSerialization;
    attr[0].val.programmaticStreamSerializationAllowed = 1;
    cfg.attrs    = attr;
    cfg.numAttrs = 1;
    cudaLaunchKernelEx(&cfg, k_main,
                       (const float4*)x, (const float4*)blocks,
                       (float4*)d_out, nblk);
}